// round 2
// baseline (speedup 1.0000x reference)
#include <cuda_runtime.h>

#define NN 200000
#define NE 6400000
#define NG 1024
#define NEMB 1032
#define TPB 256
#define NB_NODE ((NN + TPB - 1) / TPB)          // 782
#define NB_EDGE2 ((NE / 2 + TPB - 1) / TPB)     // 12500 (2 edges per thread, exact)

// Scratch: device globals (allocation-free). Two graphs processed fused.
__device__ float4 g_t[2][NN * 4];       // edge accumulators        (2 x 12.8MB)
__device__ float4 g_hs[2][NN * 4];      // layer-2 scaled features  (2 x 12.8MB)
__device__ float2 g_rec[2][NN];         // {id bits, dis} packed 8B (2 x 1.6MB)
__device__ float  g_deg[2][NN];         // in-degree counters
__device__ float4 g_tab[NEMB * 4];      // emb @ W1  (66KB, L1-resident)
__device__ float4 g_pool[2 * NG * 4];   // pooled sums
__device__ float  g_cnt[2 * NG];        // node counts per graph

__device__ __forceinline__ void red_add_v4(float4* addr, float4 v) {
    asm volatile("red.global.add.v4.f32 [%0], {%1,%2,%3,%4};"
                 :: "l"(addr), "f"(v.x), "f"(v.y), "f"(v.z), "f"(v.w)
                 : "memory");
}

// tab = emb @ W1  (1032 x 16)
__global__ void k_tab(const float* __restrict__ emb, const float* __restrict__ W1) {
    __shared__ float Ws[256];
    if (threadIdx.x < 256) Ws[threadIdx.x] = W1[threadIdx.x];
    __syncthreads();
    int r = blockIdx.x * blockDim.x + threadIdx.x;
    if (r >= NEMB) return;
    const float* x = emb + r * 16;
    float acc[16];
#pragma unroll
    for (int j = 0; j < 16; j++) acc[j] = 0.f;
#pragma unroll
    for (int k = 0; k < 16; k++) {
        float xk = __ldg(x + k);
#pragma unroll
        for (int j = 0; j < 16; j++) acc[j] += xk * Ws[k * 16 + j];
    }
    float4* o = g_tab + r * 4;
#pragma unroll
    for (int c = 0; c < 4; c++)
        o[c] = make_float4(acc[4*c], acc[4*c+1], acc[4*c+2], acc[4*c+3]);
}

// Zero everything that gets accumulated into (both graphs at once)
__global__ void k_zero() {
    int i = blockIdx.x * blockDim.x + threadIdx.x;
    if (i < NN * 4) {
        float4 z = make_float4(0.f, 0.f, 0.f, 0.f);
        g_t[0][i] = z;
        g_t[1][i] = z;
    }
    if (i < NN) { g_deg[0][i] = 0.f; g_deg[1][i] = 0.f; }
    if (i < 2 * NG * 4) g_pool[i] = make_float4(0.f, 0.f, 0.f, 0.f);
    if (i < 2 * NG) g_cnt[i] = 0.f;
}

// In-degree over dst, both graphs fused, 2 edges/thread
__global__ void k_deg(const int* __restrict__ ei0, const int* __restrict__ ei1) {
    int g = blockIdx.x >= NB_EDGE2 ? 1 : 0;
    const int* dst = (g ? ei1 : ei0) + NE;
    int i = (blockIdx.x - g * NB_EDGE2) * blockDim.x + threadIdx.x;
    int2 d = __ldg((const int2*)dst + i);
    float* deg = g_deg[g];
    atomicAdd(deg + d.x, 1.0f);
    atomicAdd(deg + d.y, 1.0f);
}

// rec = {id, rsqrt(deg+1)}; per-graph node counts
__global__ void k_embed(const int* __restrict__ ids0, const int* __restrict__ ids1,
                        const int* __restrict__ b0, const int* __restrict__ b1) {
    int g = blockIdx.x >= NB_NODE ? 1 : 0;
    int i = (blockIdx.x - g * NB_NODE) * blockDim.x + threadIdx.x;
    if (i >= NN) return;
    const int* ids = g ? ids1 : ids0;
    const int* bat = g ? b1 : b0;
    float d = rsqrtf(g_deg[g][i] + 1.0f);
    float2 r;
    r.x = __int_as_float(__ldg(ids + i));
    r.y = d;
    g_rec[g][i] = r;
    atomicAdd(&g_cnt[g * NG + __ldg(bat + i)], 1.0f);
}

// Layer-1 edge pass: t[dst] += tab[id[src]] * dis[src]
// Gather is one 8B record (32B sector); tab stays hot in L1.
__global__ void k_edge1(const int* __restrict__ ei0, const int* __restrict__ ei1) {
    int g = blockIdx.x >= NB_EDGE2 ? 1 : 0;
    const int* ei = g ? ei1 : ei0;
    int i = (blockIdx.x - g * NB_EDGE2) * blockDim.x + threadIdx.x;
    int2 s = __ldg((const int2*)ei + i);
    int2 d = __ldg((const int2*)(ei + NE) + i);
    const float2* rec = g_rec[g];
    float4* t = g_t[g];
    float2 r0 = __ldg(rec + s.x);
    float2 r1 = __ldg(rec + s.y);
#pragma unroll
    for (int k = 0; k < 2; k++) {
        float2 r = k ? r1 : r0;
        int dv = k ? d.y : d.x;
        int id = __float_as_int(r.x);
        float dis = r.y;
        const float4* tb = g_tab + (size_t)id * 4;
        float4* tp = t + (size_t)dv * 4;
#pragma unroll
        for (int c = 0; c < 4; c++) {
            float4 v = __ldg(tb + c);
            red_add_v4(tp + c, make_float4(v.x * dis, v.y * dis, v.z * dis, v.w * dis));
        }
    }
}

// y = relu(dis*(t + tab[id]*dis) + b1);  hs2 = (y @ W2) * dis;  t := 0
__global__ void k_post1(const float* __restrict__ W2, const float* __restrict__ b1p) {
    __shared__ float Ws[256];
    __shared__ float bs[16];
    if (threadIdx.x < 256) Ws[threadIdx.x] = W2[threadIdx.x];
    if (threadIdx.x < 16) bs[threadIdx.x] = b1p[threadIdx.x];
    __syncthreads();
    int g = blockIdx.x >= NB_NODE ? 1 : 0;
    int i = (blockIdx.x - g * NB_NODE) * blockDim.x + threadIdx.x;
    if (i >= NN) return;
    float2 r = g_rec[g][i];
    int id = __float_as_int(r.x);
    float d = r.y;
    float4* tp = g_t[g] + (size_t)i * 4;
    float4* hp = g_hs[g] + (size_t)i * 4;
    const float4* tb = g_tab + (size_t)id * 4;
    float y[16];
#pragma unroll
    for (int c = 0; c < 4; c++) {
        float4 t = tp[c];
        float4 h = __ldg(tb + c);
        y[4*c+0] = fmaxf(d * (t.x + h.x * d) + bs[4*c+0], 0.f);
        y[4*c+1] = fmaxf(d * (t.y + h.y * d) + bs[4*c+1], 0.f);
        y[4*c+2] = fmaxf(d * (t.z + h.z * d) + bs[4*c+2], 0.f);
        y[4*c+3] = fmaxf(d * (t.w + h.w * d) + bs[4*c+3], 0.f);
    }
    float acc[16];
#pragma unroll
    for (int j = 0; j < 16; j++) acc[j] = 0.f;
#pragma unroll
    for (int k = 0; k < 16; k++) {
        float yk = y[k];
#pragma unroll
        for (int j = 0; j < 16; j++) acc[j] += yk * Ws[k * 16 + j];
    }
    float4 z = make_float4(0.f, 0.f, 0.f, 0.f);
#pragma unroll
    for (int c = 0; c < 4; c++) {
        hp[c] = make_float4(acc[4*c] * d, acc[4*c+1] * d, acc[4*c+2] * d, acc[4*c+3] * d);
        tp[c] = z;
    }
}

// Layer-2 edge pass: t[dst] += hs2[src]
__global__ void k_edge2(const int* __restrict__ ei0, const int* __restrict__ ei1) {
    int g = blockIdx.x >= NB_EDGE2 ? 1 : 0;
    const int* ei = g ? ei1 : ei0;
    int i = (blockIdx.x - g * NB_EDGE2) * blockDim.x + threadIdx.x;
    int2 s = __ldg((const int2*)ei + i);
    int2 d = __ldg((const int2*)(ei + NE) + i);
    const float4* hs = g_hs[g];
    float4* t = g_t[g];
#pragma unroll
    for (int k = 0; k < 2; k++) {
        int sv = k ? s.y : s.x;
        int dv = k ? d.y : d.x;
        const float4* hp = hs + (size_t)sv * 4;
        float4* tp = t + (size_t)dv * 4;
        float4 v0 = __ldg(hp + 0);
        float4 v1 = __ldg(hp + 1);
        float4 v2 = __ldg(hp + 2);
        float4 v3 = __ldg(hp + 3);
        red_add_v4(tp + 0, v0);
        red_add_v4(tp + 1, v1);
        red_add_v4(tp + 2, v2);
        red_add_v4(tp + 3, v3);
    }
}

// out2 = dis*(t + hs2) + b2; pool[graph] += out2
__global__ void k_post2(const float* __restrict__ b2p,
                        const int* __restrict__ b0, const int* __restrict__ b1) {
    __shared__ float bs[16];
    if (threadIdx.x < 16) bs[threadIdx.x] = b2p[threadIdx.x];
    __syncthreads();
    int g = blockIdx.x >= NB_NODE ? 1 : 0;
    int i = (blockIdx.x - g * NB_NODE) * blockDim.x + threadIdx.x;
    if (i >= NN) return;
    const int* bat = g ? b1 : b0;
    float d = g_rec[g][i].y;
    const float4* tp = g_t[g] + (size_t)i * 4;
    const float4* hp = g_hs[g] + (size_t)i * 4;
    int gr = __ldg(bat + i);
    float4* pp = g_pool + ((size_t)(g * NG + gr)) * 4;
#pragma unroll
    for (int c = 0; c < 4; c++) {
        float4 t = tp[c];
        float4 h = hp[c];
        float4 o;
        o.x = d * (t.x + h.x) + bs[4*c+0];
        o.y = d * (t.y + h.y) + bs[4*c+1];
        o.z = d * (t.z + h.z) + bs[4*c+2];
        o.w = d * (t.w + h.w) + bs[4*c+3];
        red_add_v4(pp + c, o);
    }
}

// Mean pool + concat + FC head; out = [1024,3] then [1024,3]
__global__ void k_final(const float* __restrict__ fcW, const float* __restrict__ fcb,
                        float* __restrict__ out) {
    int b = blockIdx.x * blockDim.x + threadIdx.x;
    if (b >= NG) return;
    float inv_r = 1.0f / fmaxf(g_cnt[b], 1.0f);
    float inv_l = 1.0f / fmaxf(g_cnt[NG + b], 1.0f);
    const float4* pr = g_pool + (size_t)b * 4;
    const float4* pl = g_pool + (size_t)(NG + b) * 4;
    float v[32];
#pragma unroll
    for (int c = 0; c < 4; c++) {
        float4 r = pr[c];
        v[4*c+0] = r.x * inv_r; v[4*c+1] = r.y * inv_r;
        v[4*c+2] = r.z * inv_r; v[4*c+3] = r.w * inv_r;
        float4 l = pl[c];
        v[16+4*c+0] = l.x * inv_l; v[16+4*c+1] = l.y * inv_l;
        v[16+4*c+2] = l.z * inv_l; v[16+4*c+3] = l.w * inv_l;
    }
#pragma unroll
    for (int o = 0; o < 6; o++) {
        float s = __ldg(fcb + o);
#pragma unroll
        for (int j = 0; j < 32; j++) s += v[j] * __ldg(fcW + o * 32 + j);
        if (o < 3) out[b * 3 + o] = s;
        else       out[NG * 3 + b * 3 + (o - 3)] = s;
    }
}

extern "C" void kernel_launch(void* const* d_in, const int* in_sizes, int n_in,
                              void* d_out, int out_size) {
    const float* emb = (const float*)d_in[0];
    const float* W1  = (const float*)d_in[1];
    const float* b1  = (const float*)d_in[2];
    const float* W2  = (const float*)d_in[3];
    const float* b2  = (const float*)d_in[4];
    const float* fcW = (const float*)d_in[5];
    const float* fcb = (const float*)d_in[6];
    const int* ids0  = (const int*)d_in[7];
    const int* ei0   = (const int*)d_in[8];
    const int* b0    = (const int*)d_in[9];
    const int* ids1  = (const int*)d_in[10];
    const int* ei1   = (const int*)d_in[11];
    const int* b1i   = (const int*)d_in[12];
    float* out = (float*)d_out;

    k_tab  <<<(NEMB + TPB - 1) / TPB, TPB>>>(emb, W1);
    k_zero <<<(NN * 4 + TPB - 1) / TPB, TPB>>>();
    k_deg  <<<2 * NB_EDGE2, TPB>>>(ei0, ei1);
    k_embed<<<2 * NB_NODE, TPB>>>(ids0, ids1, b0, b1i);
    k_edge1<<<2 * NB_EDGE2, TPB>>>(ei0, ei1);
    k_post1<<<2 * NB_NODE, TPB>>>(W2, b1);
    k_edge2<<<2 * NB_EDGE2, TPB>>>(ei0, ei1);
    k_post2<<<2 * NB_NODE, TPB>>>(b2, b0, b1i);
    k_final<<<(NG + TPB - 1) / TPB, TPB>>>(fcW, fcb, out);
}